// round 1
// baseline (speedup 1.0000x reference)
#include <cuda_runtime.h>
#include <math.h>

#define Tl 1024
#define Sl 1024
#define Bb 4
#define Ee 1024
#define Hh 16
#define Dd 64
#define BHc 64
#define AW_OFF 4194304   // T*B*E

// scratch (device globals; no runtime allocation)
__device__ float g_q[BHc * Tl * Dd];
__device__ float g_k[BHc * Sl * Dd];
__device__ float g_v[BHc * Sl * Dd];
__device__ float g_x[Tl * Bb * Ee];   // attn in [m=t*B+b][e=h*64+d] layout

// ---------------------------------------------------------------------------
// GEMM 128x128x8, 256 threads, 8x8 register tiles.
// C[m,n] = sum_k A[m,k] * W[n,k]  (A row-major [M,K], W row-major [N,K])
// ---------------------------------------------------------------------------

__global__ __launch_bounds__(256) void proj_kernel(
    const float* __restrict__ q_in, const float* __restrict__ k_in,
    const float* __restrict__ v_in, const float* __restrict__ W,
    const float* __restrict__ bias)
{
    int z = blockIdx.z;
    const float* A  = (z == 0) ? q_in : ((z == 1) ? k_in : v_in);
    const float* Wz = W + (size_t)z * Ee * Ee;
    const float* bz = bias + z * Ee;
    int m0 = blockIdx.y * 128, n0 = blockIdx.x * 128;

    __shared__ __align__(16) float As[8][132];
    __shared__ __align__(16) float Ws[8][132];

    int tid = threadIdx.x;
    int lr = tid >> 1, lc = (tid & 1) * 4;
    int ty = tid >> 4, tx = tid & 15;

    float acc[8][8];
#pragma unroll
    for (int i = 0; i < 8; i++)
#pragma unroll
        for (int j = 0; j < 8; j++) acc[i][j] = 0.f;

    for (int k0 = 0; k0 < Ee; k0 += 8) {
        float4 a4 = *(const float4*)(A  + (size_t)(m0 + lr) * Ee + k0 + lc);
        float4 w4 = *(const float4*)(Wz + (size_t)(n0 + lr) * Ee + k0 + lc);
        __syncthreads();
        As[lc + 0][lr] = a4.x; As[lc + 1][lr] = a4.y;
        As[lc + 2][lr] = a4.z; As[lc + 3][lr] = a4.w;
        Ws[lc + 0][lr] = w4.x; Ws[lc + 1][lr] = w4.y;
        Ws[lc + 2][lr] = w4.z; Ws[lc + 3][lr] = w4.w;
        __syncthreads();
#pragma unroll
        for (int kk = 0; kk < 8; kk++) {
            float ra[8], rb[8];
            *(float4*)(ra)     = *(const float4*)&As[kk][ty * 8];
            *(float4*)(ra + 4) = *(const float4*)&As[kk][ty * 8 + 4];
            *(float4*)(rb)     = *(const float4*)&Ws[kk][tx * 8];
            *(float4*)(rb + 4) = *(const float4*)&Ws[kk][tx * 8 + 4];
#pragma unroll
            for (int i = 0; i < 8; i++)
#pragma unroll
                for (int j = 0; j < 8; j++) acc[i][j] += ra[i] * rb[j];
        }
    }

    float bb[8];
#pragma unroll
    for (int j = 0; j < 8; j++) bb[j] = bz[n0 + tx * 8 + j];

#pragma unroll
    for (int i = 0; i < 8; i++) {
        int m = m0 + ty * 8 + i;
        int t = m >> 2, b = m & 3;           // m = t*B + b, B=4
#pragma unroll
        for (int j = 0; j < 8; j++) {
            int n = n0 + tx * 8 + j;
            float val = acc[i][j] + bb[j];
            int h = n >> 6, d = n & 63;
            size_t idx = ((size_t)(b * Hh + h) * Tl + t) * Dd + d;
            if (z == 0)      g_q[idx] = val * 0.125f;   // D^-0.5
            else if (z == 1) g_k[idx] = val;
            else             g_v[idx] = val;
        }
    }
}

__global__ __launch_bounds__(256) void outproj_kernel(
    const float* __restrict__ W, const float* __restrict__ bias,
    float* __restrict__ out)
{
    int m0 = blockIdx.y * 128, n0 = blockIdx.x * 128;

    __shared__ __align__(16) float As[8][132];
    __shared__ __align__(16) float Ws[8][132];

    int tid = threadIdx.x;
    int lr = tid >> 1, lc = (tid & 1) * 4;
    int ty = tid >> 4, tx = tid & 15;

    float acc[8][8];
#pragma unroll
    for (int i = 0; i < 8; i++)
#pragma unroll
        for (int j = 0; j < 8; j++) acc[i][j] = 0.f;

    for (int k0 = 0; k0 < Ee; k0 += 8) {
        float4 a4 = *(const float4*)(g_x + (size_t)(m0 + lr) * Ee + k0 + lc);
        float4 w4 = *(const float4*)(W   + (size_t)(n0 + lr) * Ee + k0 + lc);
        __syncthreads();
        As[lc + 0][lr] = a4.x; As[lc + 1][lr] = a4.y;
        As[lc + 2][lr] = a4.z; As[lc + 3][lr] = a4.w;
        Ws[lc + 0][lr] = w4.x; Ws[lc + 1][lr] = w4.y;
        Ws[lc + 2][lr] = w4.z; Ws[lc + 3][lr] = w4.w;
        __syncthreads();
#pragma unroll
        for (int kk = 0; kk < 8; kk++) {
            float ra[8], rb[8];
            *(float4*)(ra)     = *(const float4*)&As[kk][ty * 8];
            *(float4*)(ra + 4) = *(const float4*)&As[kk][ty * 8 + 4];
            *(float4*)(rb)     = *(const float4*)&Ws[kk][tx * 8];
            *(float4*)(rb + 4) = *(const float4*)&Ws[kk][tx * 8 + 4];
#pragma unroll
            for (int i = 0; i < 8; i++)
#pragma unroll
                for (int j = 0; j < 8; j++) acc[i][j] += ra[i] * rb[j];
        }
    }

    float bb[8];
#pragma unroll
    for (int j = 0; j < 8; j++) bb[j] = bias[n0 + tx * 8 + j];

#pragma unroll
    for (int i = 0; i < 8; i++) {
        int m = m0 + ty * 8 + i;
#pragma unroll
        for (int j = 0; j < 8; j++) {
            int n = n0 + tx * 8 + j;
            out[(size_t)m * Ee + n] = acc[i][j] + bb[j];
        }
    }
}

// ---------------------------------------------------------------------------
// Attention: one CTA per (b, 16-row t-block). Full softmax over S=1024 in smem,
// aw accumulated over 16 heads in smem, written once.
// smem layout (floats): sc[16*1024] | awm[16*1024] | qs[16*64] | kt[128*69]
// ---------------------------------------------------------------------------

#define KT_PITCH 69
#define SMEM_FLOATS (16 * 1024 + 16 * 1024 + 16 * 64 + 128 * KT_PITCH)

__global__ __launch_bounds__(256) void attn_kernel(float* __restrict__ out)
{
    extern __shared__ float sm[];
    float* sc  = sm;                       // [16][1024] scores / probs
    float* awm = sm + 16 * 1024;           // [16][1024] head-avg accum
    float* qs  = awm + 16 * 1024;          // [16][64]
    float* kt  = qs + 16 * 64;             // [128][69] K/V tile

    int tid = threadIdx.x;
    int b  = blockIdx.x >> 6;
    int tb = blockIdx.x & 63;
    int t0 = tb * 16;

    int ip = tid >> 5;        // 0..7  -> rows 2ip, 2ip+1
    int lq = tid & 31;        // 0..31

#pragma unroll 4
    for (int c = 0; c < 64; c++) awm[c * 256 + tid] = 0.f;

    for (int h = 0; h < Hh; h++) {
        int bh = b * Hh + h;
        __syncthreads();      // previous head fully done (sc/qs/kt reads)

        // load q rows [16][64] (contiguous 1024 floats)
        const float* qb = g_q + ((size_t)bh * Tl + t0) * Dd;
#pragma unroll
        for (int c = 0; c < 4; c++) qs[c * 256 + tid] = qb[c * 256 + tid];

        // ---- scores: 8 s-tiles of 128 ----
        for (int st = 0; st < 8; st++) {
            __syncthreads();
            const float* kbase = g_k + ((size_t)bh * Sl + st * 128) * Dd;
#pragma unroll
            for (int c = 0; c < 8; c++) {
                int chunk = c * 256 + tid;       // 2048 float4 chunks
                int rr = chunk >> 4, c4 = chunk & 15;
                float4 kv = *(const float4*)(kbase + rr * Dd + c4 * 4);
                float* dst = kt + rr * KT_PITCH + c4 * 4;
                dst[0] = kv.x; dst[1] = kv.y; dst[2] = kv.z; dst[3] = kv.w;
            }
            __syncthreads();

            float a00 = 0, a01 = 0, a02 = 0, a03 = 0;
            float a10 = 0, a11 = 0, a12 = 0, a13 = 0;
            const float* q0 = qs + (2 * ip) * Dd;
            const float* q1 = qs + (2 * ip + 1) * Dd;
#pragma unroll
            for (int d = 0; d < Dd; d++) {
                float qv0 = q0[d], qv1 = q1[d];
                float k0v = kt[(lq +  0) * KT_PITCH + d];
                float k1v = kt[(lq + 32) * KT_PITCH + d];
                float k2v = kt[(lq + 64) * KT_PITCH + d];
                float k3v = kt[(lq + 96) * KT_PITCH + d];
                a00 += qv0 * k0v; a01 += qv0 * k1v; a02 += qv0 * k2v; a03 += qv0 * k3v;
                a10 += qv1 * k0v; a11 += qv1 * k1v; a12 += qv1 * k2v; a13 += qv1 * k3v;
            }
            int base0 = (2 * ip) * 1024 + st * 128 + lq;
            int base1 = base0 + 1024;
            sc[base0 +  0] = a00; sc[base0 + 32] = a01; sc[base0 + 64] = a02; sc[base0 + 96] = a03;
            sc[base1 +  0] = a10; sc[base1 + 32] = a11; sc[base1 + 64] = a12; sc[base1 + 96] = a13;
        }
        __syncthreads();

        // ---- softmax: 16 threads per row ----
        {
            int row = tid >> 4, l = tid & 15;
            float* r = sc + row * 1024;
            float mx = -INFINITY;
#pragma unroll 8
            for (int j = 0; j < 64; j++) mx = fmaxf(mx, r[l + j * 16]);
#pragma unroll
            for (int off = 8; off; off >>= 1)
                mx = fmaxf(mx, __shfl_xor_sync(0xffffffffu, mx, off, 16));
            float s = 0.f;
#pragma unroll 8
            for (int j = 0; j < 64; j++) {
                float e = __expf(r[l + j * 16] - mx);
                r[l + j * 16] = e;
                s += e;
            }
#pragma unroll
            for (int off = 8; off; off >>= 1)
                s += __shfl_xor_sync(0xffffffffu, s, off, 16);
            float inv = 1.f / s;
#pragma unroll 8
            for (int j = 0; j < 64; j++) r[l + j * 16] *= inv;
        }
        __syncthreads();

        // ---- aw accumulate (1/H = 0.0625 exact) ----
#pragma unroll 4
        for (int c = 0; c < 64; c++) {
            int off = c * 256 + tid;
            awm[off] += sc[off] * 0.0625f;
        }

        // ---- P @ V: 8 s-tiles of 128 ----
        float o00 = 0, o01 = 0, o10 = 0, o11 = 0;
        for (int st = 0; st < 8; st++) {
            __syncthreads();
            const float* vbase = g_v + ((size_t)bh * Sl + st * 128) * Dd;
#pragma unroll
            for (int c = 0; c < 8; c++) {
                int chunk = c * 256 + tid;
                int rr = chunk >> 4, c4 = chunk & 15;
                float4 vv = *(const float4*)(vbase + rr * Dd + c4 * 4);
                float* dst = kt + rr * KT_PITCH + c4 * 4;
                dst[0] = vv.x; dst[1] = vv.y; dst[2] = vv.z; dst[3] = vv.w;
            }
            __syncthreads();

            const float* p0 = sc + (2 * ip) * 1024 + st * 128;
            const float* p1 = p0 + 1024;
#pragma unroll 8
            for (int ss = 0; ss < 128; ss++) {
                float pv0 = p0[ss], pv1 = p1[ss];
                float v0 = kt[ss * KT_PITCH + lq];
                float v1 = kt[ss * KT_PITCH + lq + 32];
                o00 += pv0 * v0; o01 += pv0 * v1;
                o10 += pv1 * v0; o11 += pv1 * v1;
            }
        }

        // write attn in X layout: [m = t*4+b][e = h*64+d]
        {
            int t = t0 + 2 * ip;
            float* x0 = g_x + ((size_t)t * 4 + b) * Ee + h * Dd + lq;
            float* x1 = x0 + 4 * Ee;   // next t row
            x0[0] = o00; x0[32] = o01;
            x1[0] = o10; x1[32] = o11;
        }
    }

    __syncthreads();
    // write aw [B, T, S]
    float* awout = out + AW_OFF + (size_t)b * Tl * Sl + (size_t)t0 * Sl;
#pragma unroll 4
    for (int c = 0; c < 64; c++) {
        int off = c * 256 + tid;
        awout[off] = awm[off];
    }
}

// ---------------------------------------------------------------------------

extern "C" void kernel_launch(void* const* d_in, const int* in_sizes, int n_in,
                              void* d_out, int out_size)
{
    const float* query = (const float*)d_in[0];
    const float* key   = (const float*)d_in[1];
    const float* value = (const float*)d_in[2];
    const float* ipw   = (const float*)d_in[3];
    const float* ipb   = (const float*)d_in[4];
    const float* opw   = (const float*)d_in[5];
    const float* opb   = (const float*)d_in[6];
    float* out = (float*)d_out;

    size_t smem_bytes = SMEM_FLOATS * sizeof(float);   // 170496 B
    cudaFuncSetAttribute(attn_kernel,
                         cudaFuncAttributeMaxDynamicSharedMemorySize,
                         (int)smem_bytes);

    dim3 gp(Ee / 128, (Tl * Bb) / 128, 3);
    proj_kernel<<<gp, 256>>>(query, key, value, ipw, ipb);

    attn_kernel<<<Bb * (Tl / 16), 256, smem_bytes>>>(out);

    dim3 go(Ee / 128, (Tl * Bb) / 128);
    outproj_kernel<<<go, 256>>>(opw, opb, out);
}

// round 2
// speedup vs baseline: 2.3430x; 2.3430x over previous
#include <cuda_runtime.h>
#include <math.h>

#define Tl 1024
#define Sl 1024
#define Bb 4
#define Ee 1024
#define Hh 16
#define Dd 64
#define AW_OFF 4194304   // T*B*E

// scratch: all in natural GEMM layout [m = t*4+b][1024]
__device__ float g_q[4096 * 1024];
__device__ float g_k[4096 * 1024];
__device__ float g_v[4096 * 1024];
__device__ float g_x[4096 * 1024];

// ---------------------------------------------------------------------------
// helpers
// ---------------------------------------------------------------------------
__device__ __forceinline__ float tfr(float x) {
    unsigned r; asm("cvt.rna.tf32.f32 %0, %1;" : "=r"(r) : "f"(x));
    return __uint_as_float(r);
}
__device__ __forceinline__ unsigned tfu(float x) {
    unsigned r; asm("cvt.rna.tf32.f32 %0, %1;" : "=r"(r) : "f"(x));
    return r;
}
__device__ __forceinline__ void mma_tf32(float c[4], const unsigned a[4],
                                         const unsigned b[2]) {
    asm volatile(
        "mma.sync.aligned.m16n8k8.row.col.f32.tf32.tf32.f32 "
        "{%0,%1,%2,%3},{%4,%5,%6,%7},{%8,%9},{%0,%1,%2,%3};"
        : "+f"(c[0]), "+f"(c[1]), "+f"(c[2]), "+f"(c[3])
        : "r"(a[0]), "r"(a[1]), "r"(a[2]), "r"(a[3]), "r"(b[0]), "r"(b[1]));
}

// ---------------------------------------------------------------------------
// tf32 GEMM: C[m,n] = (sum_k A[m,k]*W[n,k] + bias[n]) * scale
// CTA tile 128x128, K=1024 in steps of 32, 256 threads = 8 warps (2m x 4n).
// smem pitch 36 (== 4 mod 32) -> conflict-free fragment loads.
// ---------------------------------------------------------------------------
#define GP 36
#define GBUF (128 * GP)

__device__ __forceinline__ void gemm128(
    const float* __restrict__ A, const float* __restrict__ W,
    const float* __restrict__ bias, float* __restrict__ C,
    float scale, int m0, int n0, float* smem)
{
    float* As = smem;               // [2][128*36]
    float* Ws = smem + 2 * GBUF;    // [2][128*36]

    int tid = threadIdx.x, lane = tid & 31, wid = tid >> 5;
    int gi = lane >> 2, ti = lane & 3;
    int wm = (wid >> 2) * 64, wn = (wid & 3) * 32;
    int lr = tid >> 3, lc = (tid & 7) * 4;

    float acc[4][4][4];
#pragma unroll
    for (int mt = 0; mt < 4; mt++)
#pragma unroll
        for (int nt = 0; nt < 4; nt++)
#pragma unroll
            for (int r = 0; r < 4; r++) acc[mt][nt][r] = 0.f;

    const float* Ag = A + (size_t)(m0 + lr) * 1024 + lc;
    const float* Wg = W + (size_t)(n0 + lr) * 1024 + lc;

    float4 ra[4], rw[4];
#pragma unroll
    for (int i = 0; i < 4; i++) {
        ra[i] = *(const float4*)(Ag + (size_t)i * 32 * 1024);
        rw[i] = *(const float4*)(Wg + (size_t)i * 32 * 1024);
    }
#pragma unroll
    for (int i = 0; i < 4; i++) {
        *(float4*)(As + (lr + 32 * i) * GP + lc) =
            make_float4(tfr(ra[i].x), tfr(ra[i].y), tfr(ra[i].z), tfr(ra[i].w));
        *(float4*)(Ws + (lr + 32 * i) * GP + lc) =
            make_float4(tfr(rw[i].x), tfr(rw[i].y), tfr(rw[i].z), tfr(rw[i].w));
    }
    __syncthreads();

#pragma unroll 2
    for (int it = 0; it < 32; ++it) {
        if (it < 31) {
#pragma unroll
            for (int i = 0; i < 4; i++) {
                ra[i] = *(const float4*)(Ag + (size_t)i * 32 * 1024 + (it + 1) * 32);
                rw[i] = *(const float4*)(Wg + (size_t)i * 32 * 1024 + (it + 1) * 32);
            }
        }
        const float* a_s = As + (it & 1) * GBUF + wm * GP;
        const float* b_s = Ws + (it & 1) * GBUF + wn * GP;
#pragma unroll
        for (int kk = 0; kk < 4; kk++) {
            unsigned af[4][4], bf[4][2];
#pragma unroll
            for (int mt = 0; mt < 4; mt++) {
                const float* p = a_s + (mt * 16 + gi) * GP + kk * 8 + ti;
                af[mt][0] = __float_as_uint(p[0]);
                af[mt][1] = __float_as_uint(p[8 * GP]);
                af[mt][2] = __float_as_uint(p[4]);
                af[mt][3] = __float_as_uint(p[8 * GP + 4]);
            }
#pragma unroll
            for (int nt = 0; nt < 4; nt++) {
                const float* p = b_s + (nt * 8 + gi) * GP + kk * 8 + ti;
                bf[nt][0] = __float_as_uint(p[0]);
                bf[nt][1] = __float_as_uint(p[4]);
            }
#pragma unroll
            for (int mt = 0; mt < 4; mt++)
#pragma unroll
                for (int nt = 0; nt < 4; nt++)
                    mma_tf32(acc[mt][nt], af[mt], bf[nt]);
        }
        if (it < 31) {
            float* dA = As + ((it + 1) & 1) * GBUF;
            float* dW = Ws + ((it + 1) & 1) * GBUF;
#pragma unroll
            for (int i = 0; i < 4; i++) {
                *(float4*)(dA + (lr + 32 * i) * GP + lc) =
                    make_float4(tfr(ra[i].x), tfr(ra[i].y), tfr(ra[i].z), tfr(ra[i].w));
                *(float4*)(dW + (lr + 32 * i) * GP + lc) =
                    make_float4(tfr(rw[i].x), tfr(rw[i].y), tfr(rw[i].z), tfr(rw[i].w));
            }
        }
        __syncthreads();
    }

#pragma unroll
    for (int mt = 0; mt < 4; mt++) {
        int m = m0 + wm + mt * 16 + gi;
#pragma unroll
        for (int nt = 0; nt < 4; nt++) {
            int n = n0 + wn + nt * 8 + 2 * ti;
            float2 bv = *(const float2*)(bias + n);
            float2 v0 = make_float2((acc[mt][nt][0] + bv.x) * scale,
                                    (acc[mt][nt][1] + bv.y) * scale);
            float2 v1 = make_float2((acc[mt][nt][2] + bv.x) * scale,
                                    (acc[mt][nt][3] + bv.y) * scale);
            *(float2*)(C + (size_t)m * 1024 + n) = v0;
            *(float2*)(C + (size_t)(m + 8) * 1024 + n) = v1;
        }
    }
}

__global__ __launch_bounds__(256) void proj_kernel(
    const float* __restrict__ q_in, const float* __restrict__ k_in,
    const float* __restrict__ v_in, const float* __restrict__ W,
    const float* __restrict__ bias)
{
    extern __shared__ float smem[];
    int z = blockIdx.z;
    const float* A = (z == 0) ? q_in : ((z == 1) ? k_in : v_in);
    float* C = (z == 0) ? g_q : ((z == 1) ? g_k : g_v);
    gemm128(A, W + (size_t)z * 1024 * 1024, bias + z * 1024, C,
            (z == 0) ? 0.125f : 1.0f, blockIdx.y * 128, blockIdx.x * 128, smem);
}

__global__ __launch_bounds__(256) void outproj_kernel(
    const float* __restrict__ W, const float* __restrict__ bias,
    float* __restrict__ out)
{
    extern __shared__ float smem[];
    gemm128(g_x, W, bias, out, 1.0f, blockIdx.y * 128, blockIdx.x * 128, smem);
}

// ---------------------------------------------------------------------------
// Attention with tf32 mma. CTA = (b, 16 t-rows), loops heads.
// smem: sc[16][1060] | awm[16][1024] | kt[2][128][68] | qs[16][68]
// ---------------------------------------------------------------------------
#define SCP 1060
#define KTP 68
#define ATT_SMEM_FLOATS (16 * SCP + 16 * 1024 + 2 * 128 * KTP + 16 * KTP)

__global__ __launch_bounds__(256) void attn_kernel(float* __restrict__ out)
{
    extern __shared__ float sm[];
    float* sc  = sm;                        // scores [16][SCP]
    float* awm = sc + 16 * SCP;             // [16][1024]
    float* kt  = awm + 16 * 1024;           // [2][128][KTP]
    float* qs  = kt + 2 * 128 * KTP;        // [16][KTP]
    float* red = kt;                        // alias buf0: [8][16][KTP]

    int tid = threadIdx.x, lane = tid & 31, wid = tid >> 5;
    int gi = lane >> 2, ti = lane & 3;
    int b = blockIdx.x >> 6;
    int t0 = (blockIdx.x & 63) * 16;

#pragma unroll 4
    for (int c = 0; c < 64; c++) awm[c * 256 + tid] = 0.f;

    for (int h = 0; h < Hh; h++) {
        int col0 = h * 64;
        __syncthreads();   // prev head's reduction reads done before kt reuse

        // ---- load Q tile [16][64] (tf32-rounded) ----
        {
            int r = tid >> 4, c4 = (tid & 15) * 4;
            float4 qv = *(const float4*)(g_q + ((size_t)(t0 + r) * 4 + b) * 1024 + col0 + c4);
            *(float4*)(qs + r * KTP + c4) =
                make_float4(tfr(qv.x), tfr(qv.y), tfr(qv.z), tfr(qv.w));
        }
        __syncthreads();

        // ---- preload Q fragments for all 8 k-steps ----
        unsigned qf[8][4];
#pragma unroll
        for (int kk = 0; kk < 8; kk++) {
            const float* p = qs + gi * KTP + kk * 8 + ti;
            qf[kk][0] = __float_as_uint(p[0]);
            qf[kk][1] = __float_as_uint(p[8 * KTP]);
            qf[kk][2] = __float_as_uint(p[4]);
            qf[kk][3] = __float_as_uint(p[8 * KTP + 4]);
        }

        // ---- QK^T: 8 s-tiles of 128, double-buffered kt ----
#pragma unroll 2
        for (int st = 0; st < 8; st++) {
            float* buf = kt + (st & 1) * 128 * KTP;
#pragma unroll
            for (int j = 0; j < 8; j++) {
                int chunk = j * 256 + tid;
                int r = chunk >> 4, c4 = (chunk & 15) * 4;
                float4 kv = *(const float4*)(g_k + ((size_t)(st * 128 + r) * 4 + b) * 1024 + col0 + c4);
                *(float4*)(buf + r * KTP + c4) =
                    make_float4(tfr(kv.x), tfr(kv.y), tfr(kv.z), tfr(kv.w));
            }
            __syncthreads();

            float s0[4] = {0, 0, 0, 0}, s1[4] = {0, 0, 0, 0};
#pragma unroll
            for (int kk = 0; kk < 8; kk++) {
                unsigned bf0[2], bf1[2];
                const float* p = buf + (wid * 16 + gi) * KTP + kk * 8 + ti;
                bf0[0] = __float_as_uint(p[0]);
                bf0[1] = __float_as_uint(p[4]);
                bf1[0] = __float_as_uint(p[8 * KTP]);
                bf1[1] = __float_as_uint(p[8 * KTP + 4]);
                mma_tf32(s0, qf[kk], bf0);
                mma_tf32(s1, qf[kk], bf1);
            }
            int scol = st * 128 + wid * 16;
            float* r0 = sc + gi * SCP + scol;
            float* r1 = sc + (gi + 8) * SCP + scol;
            *(float2*)(r0 + 2 * ti)     = make_float2(s0[0], s0[1]);
            *(float2*)(r1 + 2 * ti)     = make_float2(s0[2], s0[3]);
            *(float2*)(r0 + 8 + 2 * ti) = make_float2(s1[0], s1[1]);
            *(float2*)(r1 + 8 + 2 * ti) = make_float2(s1[2], s1[3]);
        }
        __syncthreads();

        // ---- softmax: 16 threads per row ----
        {
            int row = tid >> 4, l = tid & 15;
            float* r = sc + row * SCP;
            float mx = -INFINITY;
#pragma unroll 8
            for (int j = 0; j < 64; j++) mx = fmaxf(mx, r[l + j * 16]);
#pragma unroll
            for (int off = 8; off; off >>= 1)
                mx = fmaxf(mx, __shfl_xor_sync(0xffffffffu, mx, off, 16));
            float s = 0.f;
#pragma unroll 8
            for (int j = 0; j < 64; j++) {
                float e = __expf(r[l + j * 16] - mx);
                r[l + j * 16] = e;
                s += e;
            }
#pragma unroll
            for (int off = 8; off; off >>= 1)
                s += __shfl_xor_sync(0xffffffffu, s, off, 16);
            float inv = 1.f / s;
#pragma unroll 8
            for (int j = 0; j < 64; j++) r[l + j * 16] *= inv;
        }
        __syncthreads();

        // ---- aw accumulate ----
#pragma unroll 8
        for (int c = 0; c < 64; c++) {
            int idx = c * 256 + tid;
            awm[idx] += sc[(idx >> 10) * SCP + (idx & 1023)] * 0.0625f;
        }

        // ---- P @ V: k-split across warps (warp owns 16 s per 128-s tile) ----
        float oacc[8][4];
#pragma unroll
        for (int nt = 0; nt < 8; nt++)
#pragma unroll
            for (int r = 0; r < 4; r++) oacc[nt][r] = 0.f;

#pragma unroll 2
        for (int st = 0; st < 8; st++) {
            float* buf = kt + (st & 1) * 128 * KTP;
#pragma unroll
            for (int j = 0; j < 8; j++) {
                int chunk = j * 256 + tid;
                int r = chunk >> 4, c4 = (chunk & 15) * 4;
                float4 vv = *(const float4*)(g_v + ((size_t)(st * 128 + r) * 4 + b) * 1024 + col0 + c4);
                *(float4*)(buf + r * KTP + c4) =
                    make_float4(tfr(vv.x), tfr(vv.y), tfr(vv.z), tfr(vv.w));
            }
            __syncthreads();

#pragma unroll
            for (int j = 0; j < 2; j++) {
                unsigned pa[4];
                const float* pp = sc + gi * SCP + st * 128 + wid * 16 + j * 8 + ti;
                pa[0] = tfu(pp[0]);
                pa[1] = tfu(pp[8 * SCP]);
                pa[2] = tfu(pp[4]);
                pa[3] = tfu(pp[8 * SCP + 4]);
#pragma unroll
                for (int nt = 0; nt < 8; nt++) {
                    unsigned vb[2];
                    const float* vp = buf + (wid * 16 + j * 8 + ti) * KTP + nt * 8 + gi;
                    vb[0] = __float_as_uint(vp[0]);
                    vb[1] = __float_as_uint(vp[4 * KTP]);
                    mma_tf32(oacc[nt], pa, vb);
                }
            }
        }

        // ---- cross-warp reduction of O partials ----
        __syncthreads();   // all PV reads of kt done; red aliases kt buf0
        {
            float* myred = red + wid * 16 * KTP;
#pragma unroll
            for (int nt = 0; nt < 8; nt++) {
                *(float2*)(myred + gi * KTP + nt * 8 + 2 * ti) =
                    make_float2(oacc[nt][0], oacc[nt][1]);
                *(float2*)(myred + (gi + 8) * KTP + nt * 8 + 2 * ti) =
                    make_float2(oacc[nt][2], oacc[nt][3]);
            }
        }
        __syncthreads();
#pragma unroll
        for (int jj = 0; jj < 4; jj++) {
            int i = jj * 256 + tid;
            int r = i >> 6, c = i & 63;
            float s = 0.f;
#pragma unroll
            for (int w = 0; w < 8; w++) s += red[w * 16 * KTP + r * KTP + c];
            g_x[((size_t)(t0 + r) * 4 + b) * 1024 + col0 + c] = s;
        }
    }

    // ---- write aw [B][T][S] ----
    float* awout = out + AW_OFF + (size_t)b * Tl * Sl + (size_t)t0 * Sl;
#pragma unroll 8
    for (int c = 0; c < 64; c++) {
        int idx = c * 256 + tid;
        awout[idx] = awm[idx];
    }
}

// ---------------------------------------------------------------------------

extern "C" void kernel_launch(void* const* d_in, const int* in_sizes, int n_in,
                              void* d_out, int out_size)
{
    const float* query = (const float*)d_in[0];
    const float* key   = (const float*)d_in[1];
    const float* value = (const float*)d_in[2];
    const float* ipw   = (const float*)d_in[3];
    const float* ipb   = (const float*)d_in[4];
    const float* opw   = (const float*)d_in[5];
    const float* opb   = (const float*)d_in[6];
    float* out = (float*)d_out;

    int gemm_smem = 4 * GBUF * sizeof(float);          // 73728
    int attn_smem = ATT_SMEM_FLOATS * sizeof(float);   // 207360

    cudaFuncSetAttribute(proj_kernel,
                         cudaFuncAttributeMaxDynamicSharedMemorySize, gemm_smem);
    cudaFuncSetAttribute(outproj_kernel,
                         cudaFuncAttributeMaxDynamicSharedMemorySize, gemm_smem);
    cudaFuncSetAttribute(attn_kernel,
                         cudaFuncAttributeMaxDynamicSharedMemorySize, attn_smem);

    dim3 gp(8, 32, 3);
    proj_kernel<<<gp, 256, gemm_smem>>>(query, key, value, ipw, ipb);

    attn_kernel<<<Bb * (Tl / 16), 256, attn_smem>>>(out);

    dim3 go(8, 32);
    outproj_kernel<<<go, 256, gemm_smem>>>(opw, opb, out);
}

// round 4
// speedup vs baseline: 3.7937x; 1.6192x over previous
#include <cuda_runtime.h>
#include <math.h>

#define Tl 1024
#define Sl 1024
#define Bb 4
#define Ee 1024
#define Hh 16
#define Dd 64
#define AW_OFF 4194304   // T*B*E

// scratch (device globals)
__device__ float g_q[4096 * 1024];
__device__ float g_k[4096 * 1024];
__device__ float g_v[4096 * 1024];
__device__ float g_x[4096 * 1024];
__device__ float g_p[64 * 1024 * 1024];   // probs [BH][T][S] fp32

// ---------------------------------------------------------------------------
__device__ __forceinline__ float tfr(float x) {
    unsigned r; asm("cvt.rna.tf32.f32 %0, %1;" : "=r"(r) : "f"(x));
    return __uint_as_float(r);
}
__device__ __forceinline__ void mma_tf32(float c[4], const unsigned a[4],
                                         const unsigned b[2]) {
    asm volatile(
        "mma.sync.aligned.m16n8k8.row.col.f32.tf32.tf32.f32 "
        "{%0,%1,%2,%3},{%4,%5,%6,%7},{%8,%9},{%0,%1,%2,%3};"
        : "+f"(c[0]), "+f"(c[1]), "+f"(c[2]), "+f"(c[3])
        : "r"(a[0]), "r"(a[1]), "r"(a[2]), "r"(a[3]), "r"(b[0]), "r"(b[1]));
}

// ---------------------------------------------------------------------------
// tf32 GEMM 128x128xK(1024), 256 threads = 8 warps (2m x 4n).
// ---------------------------------------------------------------------------
#define GP 36
#define GBUF (128 * GP)

__device__ __forceinline__ void gemm128(
    const float* __restrict__ A, const float* __restrict__ W,
    const float* __restrict__ bias, float* __restrict__ C,
    float scale, int m0, int n0, float* smem, bool roundOut)
{
    float* As = smem;
    float* Ws = smem + 2 * GBUF;

    int tid = threadIdx.x, lane = tid & 31, wid = tid >> 5;
    int gi = lane >> 2, ti = lane & 3;
    int wm = (wid >> 2) * 64, wn = (wid & 3) * 32;
    int lr = tid >> 3, lc = (tid & 7) * 4;

    float acc[4][4][4];
#pragma unroll
    for (int mt = 0; mt < 4; mt++)
#pragma unroll
        for (int nt = 0; nt < 4; nt++)
#pragma unroll
            for (int r = 0; r < 4; r++) acc[mt][nt][r] = 0.f;

    const float* Ag = A + (size_t)(m0 + lr) * 1024 + lc;
    const float* Wg = W + (size_t)(n0 + lr) * 1024 + lc;

    float4 ra[4], rw[4];
#pragma unroll
    for (int i = 0; i < 4; i++) {
        ra[i] = *(const float4*)(Ag + (size_t)i * 32 * 1024);
        rw[i] = *(const float4*)(Wg + (size_t)i * 32 * 1024);
    }
#pragma unroll
    for (int i = 0; i < 4; i++) {
        *(float4*)(As + (lr + 32 * i) * GP + lc) =
            make_float4(tfr(ra[i].x), tfr(ra[i].y), tfr(ra[i].z), tfr(ra[i].w));
        *(float4*)(Ws + (lr + 32 * i) * GP + lc) =
            make_float4(tfr(rw[i].x), tfr(rw[i].y), tfr(rw[i].z), tfr(rw[i].w));
    }
    __syncthreads();

#pragma unroll 2
    for (int it = 0; it < 32; ++it) {
        if (it < 31) {
#pragma unroll
            for (int i = 0; i < 4; i++) {
                ra[i] = *(const float4*)(Ag + (size_t)i * 32 * 1024 + (it + 1) * 32);
                rw[i] = *(const float4*)(Wg + (size_t)i * 32 * 1024 + (it + 1) * 32);
            }
        }
        const float* a_s = As + (it & 1) * GBUF + wm * GP;
        const float* b_s = Ws + (it & 1) * GBUF + wn * GP;
#pragma unroll
        for (int kk = 0; kk < 4; kk++) {
            unsigned af[4][4], bf[4][2];
#pragma unroll
            for (int mt = 0; mt < 4; mt++) {
                const float* p = a_s + (mt * 16 + gi) * GP + kk * 8 + ti;
                af[mt][0] = __float_as_uint(p[0]);
                af[mt][1] = __float_as_uint(p[8 * GP]);
                af[mt][2] = __float_as_uint(p[4]);
                af[mt][3] = __float_as_uint(p[8 * GP + 4]);
            }
#pragma unroll
            for (int nt = 0; nt < 4; nt++) {
                const float* p = b_s + (nt * 8 + gi) * GP + kk * 8 + ti;
                bf[nt][0] = __float_as_uint(p[0]);
                bf[nt][1] = __float_as_uint(p[4]);
            }
#pragma unroll
            for (int mt = 0; mt < 4; mt++)
#pragma unroll
                for (int nt = 0; nt < 4; nt++)
                    mma_tf32(acc[mt][nt], af[mt], bf[nt]);
        }
        if (it < 31) {
            float* dA = As + ((it + 1) & 1) * GBUF;
            float* dW = Ws + ((it + 1) & 1) * GBUF;
#pragma unroll
            for (int i = 0; i < 4; i++) {
                *(float4*)(dA + (lr + 32 * i) * GP + lc) =
                    make_float4(tfr(ra[i].x), tfr(ra[i].y), tfr(ra[i].z), tfr(ra[i].w));
                *(float4*)(dW + (lr + 32 * i) * GP + lc) =
                    make_float4(tfr(rw[i].x), tfr(rw[i].y), tfr(rw[i].z), tfr(rw[i].w));
            }
        }
        __syncthreads();
    }

#pragma unroll
    for (int mt = 0; mt < 4; mt++) {
        int m = m0 + wm + mt * 16 + gi;
#pragma unroll
        for (int nt = 0; nt < 4; nt++) {
            int n = n0 + wn + nt * 8 + 2 * ti;
            float2 bv = *(const float2*)(bias + n);
            float v0x = (acc[mt][nt][0] + bv.x) * scale;
            float v0y = (acc[mt][nt][1] + bv.y) * scale;
            float v1x = (acc[mt][nt][2] + bv.x) * scale;
            float v1y = (acc[mt][nt][3] + bv.y) * scale;
            if (roundOut) { v0x = tfr(v0x); v0y = tfr(v0y); v1x = tfr(v1x); v1y = tfr(v1y); }
            *(float2*)(C + (size_t)m * 1024 + n) = make_float2(v0x, v0y);
            *(float2*)(C + (size_t)(m + 8) * 1024 + n) = make_float2(v1x, v1y);
        }
    }
}

__global__ __launch_bounds__(256, 2) void proj_kernel(
    const float* __restrict__ q_in, const float* __restrict__ k_in,
    const float* __restrict__ v_in, const float* __restrict__ W,
    const float* __restrict__ bias)
{
    extern __shared__ float smem[];
    int z = blockIdx.z;
    const float* A = (z == 0) ? q_in : ((z == 1) ? k_in : v_in);
    float* C = (z == 0) ? g_q : ((z == 1) ? g_k : g_v);
    gemm128(A, W + (size_t)z * 1024 * 1024, bias + z * 1024, C,
            (z == 0) ? 0.125f : 1.0f, blockIdx.y * 128, blockIdx.x * 128, smem, true);
}

__global__ __launch_bounds__(256, 2) void outproj_kernel(
    const float* __restrict__ W, const float* __restrict__ bias,
    float* __restrict__ out)
{
    extern __shared__ float smem[];
    gemm128(g_x, W, bias, out, 1.0f, blockIdx.y * 128, blockIdx.x * 128, smem, false);
}

// ---------------------------------------------------------------------------
// qk_kernel: CTA = (bh, 32 t-rows). scores -> softmax -> write P fp32 to g_p.
// smem: sc[32][1032] | kt[2][128][68] | qs[32][68]   = 210,432 B
// ---------------------------------------------------------------------------
#define SCP 1032
#define KTP 68
#define QK_SMEM_FLOATS (32 * SCP + 2 * 128 * KTP + 32 * KTP)

__global__ __launch_bounds__(256) void qk_kernel()
{
    extern __shared__ float sm[];
    float* sc = sm;                      // [32][SCP]
    float* kt = sm + 32 * SCP;           // [2][128][KTP]
    float* qs = kt + 2 * 128 * KTP;      // [32][KTP]

    int tid = threadIdx.x, lane = tid & 31, wid = tid >> 5;
    int gi = lane >> 2, ti = lane & 3;
    int bh = blockIdx.x >> 5;
    int t0 = (blockIdx.x & 31) * 32;
    int b = bh >> 4, col0 = (bh & 15) * 64;
    int wm = (wid >> 2) * 16, wn = (wid & 3) * 32;

    // load Q tile [32][64] (already tf32-rounded by proj)
#pragma unroll
    for (int i = 0; i < 2; i++) {
        int c = i * 256 + tid;
        int r = c >> 4, c4 = (c & 15) * 4;
        float4 qv = *(const float4*)(g_q + ((size_t)((t0 + r) * 4 + b)) * 1024 + col0 + c4);
        *(float4*)(qs + r * KTP + c4) = qv;
    }

    // prologue: K tile 0
    float4 kr[8];
#pragma unroll
    for (int j = 0; j < 8; j++) {
        int c = j * 256 + tid;
        int r = c >> 4, c4 = (c & 15) * 4;
        kr[j] = *(const float4*)(g_k + ((size_t)(r * 4 + b)) * 1024 + col0 + c4);
    }
#pragma unroll
    for (int j = 0; j < 8; j++) {
        int c = j * 256 + tid;
        int r = c >> 4, c4 = (c & 15) * 4;
        *(float4*)(kt + r * KTP + c4) = kr[j];
    }
    __syncthreads();

    // Q fragments
    unsigned qf[8][4];
#pragma unroll
    for (int kk = 0; kk < 8; kk++) {
        const float* p = qs + (wm + gi) * KTP + kk * 8 + ti;
        qf[kk][0] = __float_as_uint(p[0]);
        qf[kk][1] = __float_as_uint(p[8 * KTP]);
        qf[kk][2] = __float_as_uint(p[4]);
        qf[kk][3] = __float_as_uint(p[8 * KTP + 4]);
    }

#pragma unroll
    for (int st = 0; st < 8; st++) {
        if (st < 7) {
#pragma unroll
            for (int j = 0; j < 8; j++) {
                int c = j * 256 + tid;
                int r = c >> 4, c4 = (c & 15) * 4;
                kr[j] = *(const float4*)(g_k + ((size_t)(((st + 1) * 128 + r) * 4 + b)) * 1024 + col0 + c4);
            }
        }
        const float* buf = kt + (st & 1) * 128 * KTP;
        float acc[4][4];
#pragma unroll
        for (int nt = 0; nt < 4; nt++)
#pragma unroll
            for (int r = 0; r < 4; r++) acc[nt][r] = 0.f;
#pragma unroll
        for (int kk = 0; kk < 8; kk++) {
#pragma unroll
            for (int nt = 0; nt < 4; nt++) {
                unsigned bf[2];
                const float* p = buf + (wn + nt * 8 + gi) * KTP + kk * 8 + ti;
                bf[0] = __float_as_uint(p[0]);
                bf[1] = __float_as_uint(p[4]);
                mma_tf32(acc[nt], qf[kk], bf);
            }
        }
#pragma unroll
        for (int nt = 0; nt < 4; nt++) {
            int scol = st * 128 + wn + nt * 8 + 2 * ti;
            *(float2*)(sc + (wm + gi) * SCP + scol) = make_float2(acc[nt][0], acc[nt][1]);
            *(float2*)(sc + (wm + gi + 8) * SCP + scol) = make_float2(acc[nt][2], acc[nt][3]);
        }
        if (st < 7) {
            float* dst = kt + ((st + 1) & 1) * 128 * KTP;
#pragma unroll
            for (int j = 0; j < 8; j++) {
                int c = j * 256 + tid;
                int r = c >> 4, c4 = (c & 15) * 4;
                *(float4*)(dst + r * KTP + c4) = kr[j];
            }
        }
        __syncthreads();
    }

    // softmax: 8 threads per row
    {
        int row = tid >> 3, l = tid & 7;
        float* r = sc + row * SCP;
        float mx = -INFINITY;
#pragma unroll 8
        for (int j = 0; j < 128; j++) mx = fmaxf(mx, r[l + j * 8]);
#pragma unroll
        for (int off = 4; off; off >>= 1)
            mx = fmaxf(mx, __shfl_xor_sync(0xffffffffu, mx, off, 8));
        float s = 0.f;
#pragma unroll 8
        for (int j = 0; j < 128; j++) {
            float e = __expf(r[l + j * 8] - mx);
            r[l + j * 8] = e;
            s += e;
        }
#pragma unroll
        for (int off = 4; off; off >>= 1)
            s += __shfl_xor_sync(0xffffffffu, s, off, 8);
        float inv = 1.f / s;
#pragma unroll 8
        for (int j = 0; j < 128; j++) r[l + j * 8] *= inv;
    }
    __syncthreads();

    // write P (fp32, unrounded) coalesced
    float* gp = g_p + (size_t)bh * (Tl * Sl) + (size_t)t0 * Sl;
#pragma unroll
    for (int i = 0; i < 32; i++) {
        int idx = i * 256 + tid;
        int r = idx >> 8, c4 = (idx & 255) * 4;
        float4 v = *(const float4*)(sc + r * SCP + c4);
        *(float4*)(gp + r * 1024 + c4) = v;
    }
}

// ---------------------------------------------------------------------------
// pv_kernel: CTA = (bh, 128 t-rows). C[128x64] = P[128x1024] @ V[1024x64].
// smem: Pt[2][128][36] | Vs[2][32][68]  = 54,272 B
// ---------------------------------------------------------------------------
#define PTP 36
#define VTP 68
#define PV_SMEM_FLOATS (2 * 128 * PTP + 2 * 32 * VTP)

__global__ __launch_bounds__(256) void pv_kernel()
{
    extern __shared__ float sm[];
    float* Pt = sm;                     // [2][128][PTP]
    float* Vs = sm + 2 * 128 * PTP;     // [2][32][VTP]

    int tid = threadIdx.x, lane = tid & 31, wid = tid >> 5;
    int gi = lane >> 2, ti = lane & 3;
    int bh = blockIdx.x >> 3;
    int t0 = (blockIdx.x & 7) * 128;
    int b = bh >> 4, col0 = (bh & 15) * 64;
    int wm = (wid >> 1) * 32, wn = (wid & 1) * 32;

    const float* gp = g_p + (size_t)bh * (Tl * Sl) + (size_t)t0 * Sl;

    float acc[2][4][4];
#pragma unroll
    for (int mt = 0; mt < 2; mt++)
#pragma unroll
        for (int nt = 0; nt < 4; nt++)
#pragma unroll
            for (int r = 0; r < 4; r++) acc[mt][nt][r] = 0.f;

    float4 pr[4], vr[2];
    // prologue k-step 0
#pragma unroll
    for (int i = 0; i < 4; i++) {
        int idx = i * 256 + tid;
        int r = idx >> 3, c4 = (idx & 7) * 4;
        pr[i] = *(const float4*)(gp + (size_t)r * 1024 + c4);
    }
#pragma unroll
    for (int i = 0; i < 2; i++) {
        int idx = i * 256 + tid;
        int r = idx >> 4, c4 = (idx & 15) * 4;
        vr[i] = *(const float4*)(g_v + ((size_t)(r * 4 + b)) * 1024 + col0 + c4);
    }
#pragma unroll
    for (int i = 0; i < 4; i++) {
        int idx = i * 256 + tid;
        int r = idx >> 3, c4 = (idx & 7) * 4;
        *(float4*)(Pt + r * PTP + c4) =
            make_float4(tfr(pr[i].x), tfr(pr[i].y), tfr(pr[i].z), tfr(pr[i].w));
    }
#pragma unroll
    for (int i = 0; i < 2; i++) {
        int idx = i * 256 + tid;
        int r = idx >> 4, c4 = (idx & 15) * 4;
        *(float4*)(Vs + r * VTP + c4) = vr[i];   // pre-rounded by proj
    }
    __syncthreads();

#pragma unroll 2
    for (int ks = 0; ks < 32; ks++) {
        if (ks < 31) {
#pragma unroll
            for (int i = 0; i < 4; i++) {
                int idx = i * 256 + tid;
                int r = idx >> 3, c4 = (idx & 7) * 4;
                pr[i] = *(const float4*)(gp + (size_t)r * 1024 + (ks + 1) * 32 + c4);
            }
#pragma unroll
            for (int i = 0; i < 2; i++) {
                int idx = i * 256 + tid;
                int r = idx >> 4, c4 = (idx & 15) * 4;
                int s = (ks + 1) * 32 + r;
                vr[i] = *(const float4*)(g_v + ((size_t)(s * 4 + b)) * 1024 + col0 + c4);
            }
        }
        const float* Pb = Pt + (ks & 1) * 128 * PTP;
        const float* Vb = Vs + (ks & 1) * 32 * VTP;
#pragma unroll
        for (int kk = 0; kk < 4; kk++) {
            unsigned af[2][4], bf[4][2];
#pragma unroll
            for (int mt = 0; mt < 2; mt++) {
                const float* p = Pb + (wm + mt * 16 + gi) * PTP + kk * 8 + ti;
                af[mt][0] = __float_as_uint(p[0]);
                af[mt][1] = __float_as_uint(p[8 * PTP]);
                af[mt][2] = __float_as_uint(p[4]);
                af[mt][3] = __float_as_uint(p[8 * PTP + 4]);
            }
#pragma unroll
            for (int nt = 0; nt < 4; nt++) {
                const float* p = Vb + (kk * 8 + ti) * VTP + wn + nt * 8 + gi;
                bf[nt][0] = __float_as_uint(p[0]);
                bf[nt][1] = __float_as_uint(p[4 * VTP]);
            }
#pragma unroll
            for (int mt = 0; mt < 2; mt++)
#pragma unroll
                for (int nt = 0; nt < 4; nt++)
                    mma_tf32(acc[mt][nt], af[mt], bf[nt]);
        }
        if (ks < 31) {
            float* dP = Pt + ((ks + 1) & 1) * 128 * PTP;
            float* dV = Vs + ((ks + 1) & 1) * 32 * VTP;
#pragma unroll
            for (int i = 0; i < 4; i++) {
                int idx = i * 256 + tid;
                int r = idx >> 3, c4 = (idx & 7) * 4;
                *(float4*)(dP + r * PTP + c4) =
                    make_float4(tfr(pr[i].x), tfr(pr[i].y), tfr(pr[i].z), tfr(pr[i].w));
            }
#pragma unroll
            for (int i = 0; i < 2; i++) {
                int idx = i * 256 + tid;
                int r = idx >> 4, c4 = (idx & 15) * 4;
                *(float4*)(dV + r * VTP + c4) = vr[i];
            }
        }
        __syncthreads();
    }

#pragma unroll
    for (int mt = 0; mt < 2; mt++) {
        int m = t0 + wm + mt * 16 + gi;
#pragma unroll
        for (int nt = 0; nt < 4; nt++) {
            int n = col0 + wn + nt * 8 + 2 * ti;
            *(float2*)(g_x + ((size_t)(m * 4 + b)) * 1024 + n) =
                make_float2(acc[mt][nt][0], acc[mt][nt][1]);
            *(float2*)(g_x + ((size_t)((m + 8) * 4 + b)) * 1024 + n) =
                make_float2(acc[mt][nt][2], acc[mt][nt][3]);
        }
    }
}

// ---------------------------------------------------------------------------
// aw_kernel: out_aw[b][t][s] = 1/16 * sum_h g_p[b*16+h][t][s]
// 4M output floats = 1M float4 -> 4096 blocks x 256 threads.
// ---------------------------------------------------------------------------
__global__ __launch_bounds__(256) void aw_kernel(float* __restrict__ out)
{
    int f = blockIdx.x * 256 + threadIdx.x;     // float4 index, 1M total
    int t = (f >> 8) & 1023;
    int b = f >> 18;                            // 0..3
    int s4 = f & 255;
    const float* base = g_p + ((size_t)b * 16) * (Tl * Sl) + (size_t)t * 1024 + s4 * 4;
    float ax = 0.f, ay = 0.f, az = 0.f, aw = 0.f;
#pragma unroll
    for (int h = 0; h < 16; h++) {
        float4 p = *(const float4*)(base + (size_t)h * (Tl * Sl));
        ax += p.x; ay += p.y; az += p.z; aw += p.w;
    }
    *(float4*)(out + AW_OFF + (size_t)f * 4) =
        make_float4(ax * 0.0625f, ay * 0.0625f, az * 0.0625f, aw * 0.0625f);
}

// ---------------------------------------------------------------------------

extern "C" void kernel_launch(void* const* d_in, const int* in_sizes, int n_in,
                              void* d_out, int out_size)
{
    const float* query = (const float*)d_in[0];
    const float* key   = (const float*)d_in[1];
    const float* value = (const float*)d_in[2];
    const float* ipw   = (const float*)d_in[3];
    const float* ipb   = (const float*)d_in[4];
    const float* opw   = (const float*)d_in[5];
    const float* opb   = (const float*)d_in[6];
    float* out = (float*)d_out;

    int gemm_smem = 4 * GBUF * sizeof(float);            // 73,728
    int qk_smem   = QK_SMEM_FLOATS * sizeof(float);      // 210,432
    int pv_smem   = PV_SMEM_FLOATS * sizeof(float);      // 54,272

    cudaFuncSetAttribute(proj_kernel,
                         cudaFuncAttributeMaxDynamicSharedMemorySize, gemm_smem);
    cudaFuncSetAttribute(outproj_kernel,
                         cudaFuncAttributeMaxDynamicSharedMemorySize, gemm_smem);
    cudaFuncSetAttribute(qk_kernel,
                         cudaFuncAttributeMaxDynamicSharedMemorySize, qk_smem);
    cudaFuncSetAttribute(pv_kernel,
                         cudaFuncAttributeMaxDynamicSharedMemorySize, pv_smem);

    dim3 gp(8, 32, 3);
    proj_kernel<<<gp, 256, gemm_smem>>>(query, key, value, ipw, ipb);

    qk_kernel<<<64 * 32, 256, qk_smem>>>();

    pv_kernel<<<64 * 8, 256, pv_smem>>>();

    dim3 go(8, 32);
    outproj_kernel<<<go, 256, gemm_smem>>>(opw, opb, out);

    aw_kernel<<<4096, 256>>>(out);
}